// round 2
// baseline (speedup 1.0000x reference)
#include <cuda_runtime.h>
#include <stdint.h>

// Problem shape: X (B=4, L=8192, D=32, N=32) fp32, cumsum along L.
// Inner = D*N = 1024 contiguous floats per (b, l). Chain stride = 4096 B.
#define BB      4
#define LL      8192
#define INNER   1024
#define CHUNK   32
#define NT      (LL / CHUNK)      // 256 L-tiles per batch
#define NTILES  (BB * NT)         // 1024 tiles total

// Decoupled-lookback state: one packed {flag:32 | value_bits:32} word per
// (tile, lane). flag semantics (per launch epoch E, E starts at 2, +=2/launch):
//   flag <  E   : stale (previous launch) -> spin
//   flag == E   : aggregate available
//   flag == E+1 : inclusive prefix available
__device__ unsigned long long g_state[(size_t)NTILES * INNER];
__device__ unsigned int g_epoch  = 0;
__device__ unsigned int g_ticket = 0;

__device__ __forceinline__ unsigned long long ld_relaxed_u64(const unsigned long long* p) {
    unsigned long long v;
    asm volatile("ld.relaxed.gpu.global.b64 %0, [%1];" : "=l"(v) : "l"(p));
    return v;
}
__device__ __forceinline__ void st_relaxed_u64(unsigned long long* p, unsigned long long v) {
    asm volatile("st.relaxed.gpu.global.b64 [%0], %1;" :: "l"(p), "l"(v));
}
__device__ __forceinline__ unsigned long long pack_fv(unsigned int flag, float val) {
    return ((unsigned long long)flag << 32) | (unsigned long long)__float_as_uint(val);
}

__global__ void scan_init_kernel() {
    // One thread: bump epoch (invalidates all prior-state flags), reset ticket.
    g_epoch += 2;
    g_ticket = 0;
    __threadfence();
}

__global__ __launch_bounds__(1024, 1)
void blelloch_scan_kernel(const float* __restrict__ X, float* __restrict__ Y) {
    __shared__ unsigned int s_tile;
    __shared__ unsigned int s_epoch;

    if (threadIdx.x == 0) {
        // Relaxed gpu-scope load: init kernel wrote this earlier in the stream;
        // the kernel-launch boundary orders it.
        unsigned int e;
        asm volatile("ld.relaxed.gpu.global.b32 %0, [%1];" : "=r"(e) : "l"(&g_epoch));
        s_epoch = e;
        s_tile  = atomicAdd(&g_ticket, 1u);
    }
    __syncthreads();

    const unsigned int epoch = s_epoch;
    const unsigned int t     = s_tile;
    const int b     = (int)(t % BB);       // ticket order => predecessor tile
    const int ltile = (int)(t / BB);       //   (b, ltile-1) has ticket t-4 < t
    const int lane  = threadIdx.x;

    const size_t base = ((size_t)b * LL + (size_t)ltile * CHUNK) * INNER + lane;
    const float* __restrict__ p = X + base;

    // Load 32 strided values (each row-load fully coalesced across the CTA).
    float v[CHUNK];
#pragma unroll
    for (int i = 0; i < CHUNK; ++i) v[i] = p[(size_t)i * INNER];

    // In-register inclusive scan along L.
#pragma unroll
    for (int i = 1; i < CHUNK; ++i) v[i] += v[i - 1];
    const float total = v[CHUNK - 1];

    unsigned long long* my_state =
        &g_state[((size_t)(b * NT + ltile)) * INNER + lane];

    float excl = 0.0f;
    if (ltile == 0) {
        // Inclusive prefix == local total; publish immediately.
        st_relaxed_u64(my_state, pack_fv(epoch + 1u, total));
    } else {
        // Publish aggregate first so successors can make progress.
        st_relaxed_u64(my_state, pack_fv(epoch, total));

        // Per-thread decoupled lookback (flag+value in one atomic 8B word,
        // so no fences or block syncs needed).
        int pt = ltile - 1;
        const unsigned long long* st_row =
            &g_state[((size_t)(b * NT)) * INNER + lane];
        while (true) {
            unsigned long long w = ld_relaxed_u64(st_row + (size_t)pt * INNER);
            unsigned int f = (unsigned int)(w >> 32);
            if (f < epoch) {            // stale -> predecessor not published yet
                __nanosleep(40);        // yield SMSP instead of hammering L2
                continue;
            }
            excl += __uint_as_float((unsigned int)w);
            if (f == epoch) { --pt; continue; }           // aggregate -> keep going
            break;                                        // inclusive -> done
        }
        // Publish our inclusive prefix ASAP to unblock successors.
        st_relaxed_u64(my_state, pack_fv(epoch + 1u, excl + total));
    }

    // Write outputs (coalesced 4 KB rows).
    float* __restrict__ q = Y + base;
#pragma unroll
    for (int i = 0; i < CHUNK; ++i) q[(size_t)i * INNER] = v[i] + excl;
}

extern "C" void kernel_launch(void* const* d_in, const int* in_sizes, int n_in,
                              void* d_out, int out_size) {
    const float* X = (const float*)d_in[0];
    float*       Y = (float*)d_out;
    (void)in_sizes; (void)n_in; (void)out_size;

    scan_init_kernel<<<1, 1>>>();
    blelloch_scan_kernel<<<NTILES, 1024>>>(X, Y);
}

// round 3
// speedup vs baseline: 1.0875x; 1.0875x over previous
#include <cuda_runtime.h>
#include <stdint.h>

// X (B=4, L=8192, D=32, N=32) fp32, cumsum along L (axis=1).
// Inner = D*N = 1024 contiguous floats per (b,l).
#define BB      4
#define LL      8192
#define INNER   1024
#define SEGW    256                    // lanes per CTA (segment width)
#define NSEG    (INNER / SEGW)         // 4 segments
#define CHUNK   32                     // L rows per tile
#define NT      (LL / CHUNK)           // 256 L-tiles per chain
#define NCHAIN  (BB * NSEG)            // 16 independent (b,seg) chains
#define NTILES  (NCHAIN * NT)          // 4096 tiles per launch
#define LOOKW   8                      // lookback window (independent loads)

// Decoupled-lookback state: packed {flag:32 | value_bits:32} per (tile, lane).
// Per-launch epoch E = (first_ticket >> 12) + 1 (monotonic across launches,
// g_ticket is NEVER reset -> no init kernel needed).
//   flag <  2E   : stale (earlier launch)
//   flag == 2E   : aggregate available
//   flag == 2E+1 : inclusive prefix available
__device__ unsigned long long g_state[(size_t)NTILES * SEGW];
__device__ unsigned int g_ticket = 0;   // monotonic forever

__device__ __forceinline__ unsigned long long ld_relaxed_u64(const unsigned long long* p) {
    unsigned long long v;
    asm volatile("ld.relaxed.gpu.global.b64 %0, [%1];" : "=l"(v) : "l"(p));
    return v;
}
__device__ __forceinline__ void st_relaxed_u64(unsigned long long* p, unsigned long long v) {
    asm volatile("st.relaxed.gpu.global.b64 [%0], %1;" :: "l"(p), "l"(v));
}
__device__ __forceinline__ unsigned long long pack_fv(unsigned int flag, float val) {
    return ((unsigned long long)flag << 32) | (unsigned long long)__float_as_uint(val);
}

__global__ __launch_bounds__(SEGW, 4)
void scan_kernel(const float* __restrict__ X, float* __restrict__ Y) {
    __shared__ unsigned int s_ticket;
    if (threadIdx.x == 0) s_ticket = atomicAdd(&g_ticket, 1u);
    __syncthreads();

    const unsigned int t      = s_ticket;
    const unsigned int tloc   = t & (NTILES - 1u);         // tile within launch
    const unsigned int epoch  = (t >> 12) + 1u;            // launch-unique
    const unsigned int fbase  = epoch * 2u;                // agg flag; incl = fbase+1

    // chain = (b, seg); predecessor tile has ticket t - NCHAIN < t.
    const int chain = (int)(tloc % NCHAIN);
    const int ltile = (int)(tloc / NCHAIN);
    const int b     = chain >> 2;       // NSEG = 4
    const int seg   = chain & 3;
    const int lane  = (int)threadIdx.x;

    const size_t base = ((size_t)b * LL + (size_t)ltile * CHUNK) * INNER
                      + (size_t)seg * SEGW + lane;
    const float* __restrict__ p = X + base;

    // 32 coalesced strided loads (1 KB per row per CTA), all independent.
    float v[CHUNK];
#pragma unroll
    for (int i = 0; i < CHUNK; ++i) v[i] = p[(size_t)i * INNER];

    // In-register inclusive scan along L.
#pragma unroll
    for (int i = 1; i < CHUNK; ++i) v[i] += v[i - 1];
    const float total = v[CHUNK - 1];

    const size_t chain_base = ((size_t)chain * NT) * SEGW + lane;
    unsigned long long* my_state = &g_state[chain_base + (size_t)ltile * SEGW];

    float excl = 0.0f;
    if (ltile == 0) {
        st_relaxed_u64(my_state, pack_fv(fbase + 1u, total));
    } else {
        // Publish aggregate first so successors can make progress.
        st_relaxed_u64(my_state, pack_fv(fbase, total));

        // Windowed per-thread lookback: LOOKW independent loads per round.
        const unsigned long long* st_row = &g_state[chain_base];
        int pt = ltile - 1;
        for (;;) {
            unsigned long long w[LOOKW];
            const int n = (pt + 1 < LOOKW) ? (pt + 1) : LOOKW;
#pragma unroll
            for (int j = 0; j < LOOKW; ++j)
                if (j < n) w[j] = ld_relaxed_u64(st_row + (size_t)(pt - j) * SEGW);

            int consumed = 0;
            bool done = false;
#pragma unroll
            for (int j = 0; j < LOOKW; ++j) {
                if (j >= n || done) continue;
                unsigned int f = (unsigned int)(w[j] >> 32);
                if (f < fbase) break;                          // stale: stop here
                excl += __uint_as_float((unsigned int)w[j]);
                ++consumed;
                if (f == fbase + 1u) done = true;              // hit an inclusive
            }
            pt -= consumed;
            if (done) break;
            if (consumed == 0) __nanosleep(32);                // head still stale
        }
        // Publish inclusive prefix ASAP to unblock successors.
        st_relaxed_u64(my_state, pack_fv(fbase + 1u, excl + total));
    }

    // Coalesced output stores.
    float* __restrict__ q = Y + base;
#pragma unroll
    for (int i = 0; i < CHUNK; ++i) q[(size_t)i * INNER] = v[i] + excl;
}

extern "C" void kernel_launch(void* const* d_in, const int* in_sizes, int n_in,
                              void* d_out, int out_size) {
    const float* X = (const float*)d_in[0];
    float*       Y = (float*)d_out;
    (void)in_sizes; (void)n_in; (void)out_size;
    scan_kernel<<<NTILES, SEGW>>>(X, Y);
}

// round 5
// speedup vs baseline: 1.1304x; 1.0394x over previous
#include <cuda_runtime.h>
#include <stdint.h>

// X (B=4, L=8192, D=32, N=32) fp32, cumsum along L (axis=1).
// Inner = D*N = 1024 contiguous floats per (b,l).
#define BB      4
#define LL      8192
#define INNER   1024
#define SEGW    256                    // lanes per CTA (segment width)
#define NSEG    (INNER / SEGW)         // 4 segments
#define CHUNK   16                     // L rows per tile
#define NT      (LL / CHUNK)           // 512 L-tiles per chain
#define NCHAIN  (BB * NSEG)            // 16 independent (b,seg) chains
#define NTILES  (NCHAIN * NT)          // 8192 tiles per launch
#define GRID    592                    // persistent CTAs (4 per SM x 148 SMs)
#define LOOKW   4                      // lookback window (independent loads)

// Decoupled-lookback state: packed {flag:32 | value_bits:32} per (tile, lane).
//   flag <  2E   : stale (earlier launch)      (E = epoch, bumped each launch)
//   flag == 2E   : aggregate available
//   flag == 2E+1 : inclusive prefix available
__device__ unsigned long long g_state[(size_t)NTILES * SEGW];   // 16 MiB (L2-resident)
__device__ unsigned int g_epoch  = 0;
__device__ unsigned int g_ticket = 0;

__device__ __forceinline__ unsigned long long ld_relaxed_u64(const unsigned long long* p) {
    unsigned long long v;
    asm volatile("ld.relaxed.gpu.global.b64 %0, [%1];" : "=l"(v) : "l"(p));
    return v;
}
__device__ __forceinline__ void st_relaxed_u64(unsigned long long* p, unsigned long long v) {
    asm volatile("st.relaxed.gpu.global.b64 [%0], %1;" :: "l"(p), "l"(v));
}
__device__ __forceinline__ unsigned long long pack_fv(unsigned int flag, float val) {
    return ((unsigned long long)flag << 32) | (unsigned long long)__float_as_uint(val);
}

__global__ void scan_init_kernel() {
    g_epoch += 1;
    g_ticket = 0;
    __threadfence();
}

__device__ __forceinline__ size_t tile_base(int tile, int lane) {
    const int chain = tile & (NCHAIN - 1);
    const int ltile = tile >> 4;               // NCHAIN = 16
    const int b     = chain >> 2;              // NSEG = 4
    const int seg   = chain & 3;
    return ((size_t)b * LL + (size_t)ltile * CHUNK) * INNER
         + (size_t)seg * SEGW + lane;
}

__global__ __launch_bounds__(SEGW, 4)
void scan_kernel(const float* __restrict__ X, float* __restrict__ Y) {
    __shared__ unsigned int s_t;
    __shared__ unsigned int s_epoch;

    const int lane = (int)threadIdx.x;

    if (threadIdx.x == 0) {
        unsigned int e;
        asm volatile("ld.relaxed.gpu.global.b32 %0, [%1];" : "=r"(e) : "l"(&g_epoch));
        s_epoch = e;
        s_t     = atomicAdd(&g_ticket, 1u);
    }
    __syncthreads();
    const unsigned int fbase = s_epoch * 2u;   // agg flag; incl = fbase+1
    int t0 = (int)s_t;
    if (t0 >= NTILES) return;

    // Preload first tile.
    float v[CHUNK];
    {
        const float* p = X + tile_base(t0, lane);
#pragma unroll
        for (int i = 0; i < CHUNK; ++i) v[i] = p[(size_t)i * INNER];
    }

    for (;;) {
        // ---- local inclusive scan of current tile ----
#pragma unroll
        for (int i = 1; i < CHUNK; ++i) v[i] += v[i - 1];
        const float total = v[CHUNK - 1];

        const int chain = t0 & (NCHAIN - 1);
        const int ltile = t0 >> 4;
        const size_t chain_base = ((size_t)chain * NT) * SEGW + lane;
        unsigned long long* my_state = &g_state[chain_base + (size_t)ltile * SEGW];

        // Publish aggregate (or inclusive for tile 0) immediately.
        st_relaxed_u64(my_state,
                       pack_fv(ltile == 0 ? fbase + 1u : fbase, total));

        // ---- acquire next ticket & issue its loads (overlap with lookback) ----
        __syncthreads();                       // all threads consumed previous s_t
        if (threadIdx.x == 0) s_t = atomicAdd(&g_ticket, 1u);
        __syncthreads();
        const int t1 = (int)s_t;

        float vn[CHUNK];
        if (t1 < NTILES) {
            const float* p = X + tile_base(t1, lane);
#pragma unroll
            for (int i = 0; i < CHUNK; ++i) vn[i] = p[(size_t)i * INNER];
        }

        // ---- decoupled lookback (window of LOOKW independent loads) ----
        float excl = 0.0f;
        if (ltile != 0) {
            const unsigned long long* st_row = &g_state[chain_base];
            int pt = ltile - 1;
            for (;;) {
                unsigned long long w[LOOKW];
                const int n = (pt + 1 < LOOKW) ? (pt + 1) : LOOKW;
#pragma unroll
                for (int j = 0; j < LOOKW; ++j)
                    if (j < n) w[j] = ld_relaxed_u64(st_row + (size_t)(pt - j) * SEGW);

                int consumed = 0;
                bool done = false;
#pragma unroll
                for (int j = 0; j < LOOKW; ++j) {
                    if (j >= n || done) continue;
                    unsigned int f = (unsigned int)(w[j] >> 32);
                    if (f < fbase) break;                      // stale: stop
                    excl += __uint_as_float((unsigned int)w[j]);
                    ++consumed;
                    if (f == fbase + 1u) done = true;          // found inclusive
                }
                pt -= consumed;
                if (done) break;
                if (consumed == 0) __nanosleep(32);
            }
            // Publish inclusive prefix ASAP to unblock successors.
            st_relaxed_u64(my_state, pack_fv(fbase + 1u, excl + total));
        }

        // ---- store outputs (coalesced) ----
        {
            float* q = Y + tile_base(t0, lane);
#pragma unroll
            for (int i = 0; i < CHUNK; ++i) q[(size_t)i * INNER] = v[i] + excl;
        }

        if (t1 >= NTILES) break;
        t0 = t1;
#pragma unroll
        for (int i = 0; i < CHUNK; ++i) v[i] = vn[i];
    }
}

extern "C" void kernel_launch(void* const* d_in, const int* in_sizes, int n_in,
                              void* d_out, int out_size) {
    const float* X = (const float*)d_in[0];
    float*       Y = (float*)d_out;
    (void)in_sizes; (void)n_in; (void)out_size;

    scan_init_kernel<<<1, 1>>>();
    scan_kernel<<<GRID, SEGW>>>(X, Y);
}

// round 7
// speedup vs baseline: 1.2098x; 1.0703x over previous
#include <cuda_runtime.h>
#include <stdint.h>

// X (B=4, L=8192, D=32, N=32) fp32, cumsum along L (axis=1).
// Inner = D*N = 1024 contiguous floats per (b,l).
#define BB      4
#define LL      8192
#define INNER   1024
#define SEGW    256                    // lanes per CTA (segment width)
#define NSEG    (INNER / SEGW)         // 4 segments
#define CHUNK   32                     // L rows per tile
#define NT      (LL / CHUNK)           // 256 L-tiles per chain
#define NCHAIN  (BB * NSEG)            // 16 independent (b,seg) chains
#define NTILES  (NCHAIN * NT)          // 4096 tiles per launch
#define GRID    592                    // persistent CTAs (4/SM x 148 SMs)
#define LOOKW   6                      // lookback window (independent loads)
#define TILE_BYTES (CHUNK * SEGW * 4)  // 32 KB smem staging per CTA

// Decoupled-lookback state: packed {flag:32 | value_bits:32} per (tile, lane).
//   flag <  2E   : stale (earlier launch)      (E = epoch, bumped each launch)
//   flag == 2E   : aggregate available
//   flag == 2E+1 : inclusive prefix available
__device__ unsigned long long g_state[(size_t)NTILES * SEGW];   // 8 MiB (L2-resident)
__device__ unsigned int g_epoch  = 0;
__device__ unsigned int g_ticket = 0;

__device__ __forceinline__ unsigned long long ld_relaxed_u64(const unsigned long long* p) {
    unsigned long long v;
    asm volatile("ld.relaxed.gpu.global.b64 %0, [%1];" : "=l"(v) : "l"(p));
    return v;
}
__device__ __forceinline__ void st_relaxed_u64(unsigned long long* p, unsigned long long v) {
    asm volatile("st.relaxed.gpu.global.b64 [%0], %1;" :: "l"(p), "l"(v));
}
__device__ __forceinline__ unsigned long long pack_fv(unsigned int flag, float val) {
    return ((unsigned long long)flag << 32) | (unsigned long long)__float_as_uint(val);
}
__device__ __forceinline__ void cp_async16(uint32_t smem_addr, const void* gmem) {
    asm volatile("cp.async.cg.shared.global [%0], [%1], 16;"
                 :: "r"(smem_addr), "l"(gmem));
}
__device__ __forceinline__ void cp_async_commit() {
    asm volatile("cp.async.commit_group;");
}
__device__ __forceinline__ void cp_async_wait0() {
    asm volatile("cp.async.wait_group 0;");
}

__global__ void scan_init_kernel() {
    g_epoch += 1;
    g_ticket = 0;
    __threadfence();
}

// Element index of row 0, lane 0 of a tile (lane added separately).
__device__ __forceinline__ size_t tile_row0(int tile) {
    const int chain = tile & (NCHAIN - 1);
    const int ltile = tile >> 4;               // NCHAIN = 16
    const int b     = chain >> 2;              // NSEG = 4
    const int seg   = chain & 3;
    return ((size_t)b * LL + (size_t)ltile * CHUNK) * INNER + (size_t)seg * SEGW;
}

__global__ __launch_bounds__(SEGW, 4)
void scan_kernel(const float* __restrict__ X, float* __restrict__ Y) {
    __shared__ float s_buf[CHUNK * SEGW];      // 32 KB staging
    __shared__ unsigned int s_t;
    __shared__ unsigned int s_epoch;

    const int tid  = (int)threadIdx.x;
    const int lane = tid;

    uint32_t s_base;
    asm("{ .reg .u64 t; cvta.to.shared.u64 t, %1; cvt.u32.u64 %0, t; }"
        : "=r"(s_base) : "l"(s_buf));

    if (tid == 0) {
        unsigned int e;
        asm volatile("ld.relaxed.gpu.global.b32 %0, [%1];" : "=r"(e) : "l"(&g_epoch));
        s_epoch = e;
        s_t     = atomicAdd(&g_ticket, 1u);
    }
    __syncthreads();
    const unsigned int fbase = s_epoch * 2u;   // agg flag; incl = fbase+1
    int t0 = (int)s_t;
    if (t0 >= NTILES) return;

    // cp.async sweep geometry: 8 sweeps of 4 KB; thread covers 16 B per sweep.
    const int sub  = tid >> 6;                 // row-within-4 group
    const int colb = (tid & 63) * 16;          // byte column within row (0..1008)
    const uint32_t s_dst0 = s_base + (uint32_t)(sub * 1024 + colb);

    // Prologue: prefetch first tile.
    {
        const char* src = (const char*)(X + tile_row0(t0));
#pragma unroll
        for (int s = 0; s < CHUNK / 4; ++s)
            cp_async16(s_dst0 + (uint32_t)s * 4096u,
                       src + (size_t)(s * 4 + sub) * (INNER * 4) + colb);
        cp_async_commit();
    }

    for (;;) {
        cp_async_wait0();
        __syncthreads();                       // staged tile visible to all

        // ---- load from smem + local inclusive scan ----
        float v[CHUNK];
#pragma unroll
        for (int i = 0; i < CHUNK; ++i) v[i] = s_buf[i * SEGW + lane];
#pragma unroll
        for (int i = 1; i < CHUNK; ++i) v[i] += v[i - 1];
        const float total = v[CHUNK - 1];

        const int chain = t0 & (NCHAIN - 1);
        const int ltile = t0 >> 4;
        const size_t chain_base = ((size_t)chain * NT) * SEGW + lane;
        unsigned long long* my_state = &g_state[chain_base + (size_t)ltile * SEGW];

        // Publish aggregate (inclusive for ltile 0) immediately.
        st_relaxed_u64(my_state,
                       pack_fv(ltile == 0 ? fbase + 1u : fbase, total));

        // Next ticket. (Write-after-read on s_t is safe: last read was before
        // the barrier above, in the previous iteration.)
        if (tid == 0) s_t = atomicAdd(&g_ticket, 1u);
        __syncthreads();                       // LDS drained + s_t visible
        const int t1 = (int)s_t;

        // Prefetch next tile into the (now reusable) buffer; overlaps lookback.
        if (t1 < NTILES) {
            const char* src = (const char*)(X + tile_row0(t1));
#pragma unroll
            for (int s = 0; s < CHUNK / 4; ++s)
                cp_async16(s_dst0 + (uint32_t)s * 4096u,
                           src + (size_t)(s * 4 + sub) * (INNER * 4) + colb);
            cp_async_commit();
        }

        // ---- decoupled lookback (LOOKW independent loads per round) ----
        float excl = 0.0f;
        if (ltile != 0) {
            const unsigned long long* st_row = &g_state[chain_base];
            int pt = ltile - 1;
            for (;;) {
                unsigned long long w[LOOKW];
                const int n = (pt + 1 < LOOKW) ? (pt + 1) : LOOKW;
#pragma unroll
                for (int j = 0; j < LOOKW; ++j)
                    if (j < n) w[j] = ld_relaxed_u64(st_row + (size_t)(pt - j) * SEGW);

                int consumed = 0;
                bool done = false;
#pragma unroll
                for (int j = 0; j < LOOKW; ++j) {
                    if (j >= n || done) continue;
                    unsigned int f = (unsigned int)(w[j] >> 32);
                    if (f < fbase) break;                      // stale: stop
                    excl += __uint_as_float((unsigned int)w[j]);
                    ++consumed;
                    if (f == fbase + 1u) done = true;          // found inclusive
                }
                pt -= consumed;
                if (done) break;
                if (consumed == 0) __nanosleep(32);
            }
            st_relaxed_u64(my_state, pack_fv(fbase + 1u, excl + total));
        }

        // ---- store outputs (coalesced) ----
        {
            float* q = Y + tile_row0(t0) + lane;
#pragma unroll
            for (int i = 0; i < CHUNK; ++i) q[(size_t)i * INNER] = v[i] + excl;
        }

        if (t1 >= NTILES) break;
        t0 = t1;
    }
}

extern "C" void kernel_launch(void* const* d_in, const int* in_sizes, int n_in,
                              void* d_out, int out_size) {
    const float* X = (const float*)d_in[0];
    float*       Y = (float*)d_out;
    (void)in_sizes; (void)n_in; (void)out_size;

    scan_init_kernel<<<1, 1>>>();
    scan_kernel<<<GRID, SEGW>>>(X, Y);
}